// round 9
// baseline (speedup 1.0000x reference)
#include <cuda_runtime.h>
#include <math.h>

// Fixed problem shape (B, N, M) = (64, 2048, 256)
#define BB 64
#define NN 2048
#define MM 256
#define EPS_COS 1e-16f
#define EPS_NRM 1e-8f
#define NSPLIT 16            // blocks per b in each phase
#define CHUNK (NN / NSPLIT)  // 128 rows per block

// Static scratch (allocation-free rule). Zero-initialized at module load.
__device__ float g_scores[BB * NN];          // dot/mem_nrm (k_nrm applied in softmax)
__device__ float g_a[BB * NN];               // w_r * (1 - w_lu_prev)
__device__ float g_c[BB];                    // sum(w_r * w_w)
__device__ float g_part[BB * NSPLIT * MM];
__device__ unsigned int g_cnt_a[BB];         // phase counters (reset by consumer)
__device__ unsigned int g_cnt_b[BB];

// ===================================================================
// Kernel A: score (streaming pass 1) + fused per-b softmax.
// grid = (BB, NSPLIT), block = 256 (8 warps, warp-per-row, 16 iters).
// b varies fastest across blockIdx.x so same-b blocks spread across waves.
// Last block of each b performs the softmax for that b.
// ===================================================================
__global__ void __launch_bounds__(256)
score_softmax_kernel(const float4* __restrict__ mem4,
                     const float*  __restrict__ k,
                     const float*  __restrict__ g,
                     const float*  __restrict__ w_prev,
                     const int*    __restrict__ w_lu_prev) {
    int b     = blockIdx.x;
    int split = blockIdx.y;
    int t     = threadIdx.x;
    int warp  = t >> 5;
    int lane  = t & 31;

    __shared__ float ke[MM];
    __shared__ float red[8];
    __shared__ unsigned int s_old;

    ke[t] = k[b * MM + t] + EPS_COS;
    __syncthreads();

    // ---- phase 1: scores for this block's 128 rows ----
    int n0 = split * CHUNK;
    int m0 = lane * 8;
    #pragma unroll 2
    for (int it = 0; it < CHUNK / 8; it++) {
        int n   = n0 + it * 8 + warp;
        int row = b * NN + n;
        const float4* p = mem4 + (size_t)row * (MM / 4) + lane * 2;
        float4 v0 = p[0];
        float4 v1 = p[1];

        float dot = 0.f, ss = 0.f, me;
        me = v0.x + EPS_COS; dot = fmaf(me, ke[m0 + 0], dot); ss = fmaf(me, me, ss);
        me = v0.y + EPS_COS; dot = fmaf(me, ke[m0 + 1], dot); ss = fmaf(me, me, ss);
        me = v0.z + EPS_COS; dot = fmaf(me, ke[m0 + 2], dot); ss = fmaf(me, me, ss);
        me = v0.w + EPS_COS; dot = fmaf(me, ke[m0 + 3], dot); ss = fmaf(me, me, ss);
        me = v1.x + EPS_COS; dot = fmaf(me, ke[m0 + 4], dot); ss = fmaf(me, me, ss);
        me = v1.y + EPS_COS; dot = fmaf(me, ke[m0 + 5], dot); ss = fmaf(me, me, ss);
        me = v1.z + EPS_COS; dot = fmaf(me, ke[m0 + 6], dot); ss = fmaf(me, me, ss);
        me = v1.w + EPS_COS; dot = fmaf(me, ke[m0 + 7], dot); ss = fmaf(me, me, ss);

        #pragma unroll
        for (int o = 16; o; o >>= 1) {
            dot += __shfl_xor_sync(0xffffffffu, dot, o);
            ss  += __shfl_xor_sync(0xffffffffu, ss,  o);
        }
        if (lane == 0) {
            float nrm = fmaxf(sqrtf(ss), EPS_NRM);
            g_scores[row] = dot / nrm;
        }
    }

    // ---- handoff: last block of this b does the softmax ----
    __syncthreads();
    __threadfence();                       // release: scores visible before count
    if (t == 0) s_old = atomicAdd(&g_cnt_a[b], 1u);
    __syncthreads();
    if (s_old != NSPLIT - 1) return;
    __threadfence();                       // acquire: see all blocks' scores

    int lane2 = t & 31, wid = t >> 5;

    // k_nrm for this b (ke[] already holds k+eps)
    float kv = ke[t];
    float ss = kv * kv;
    #pragma unroll
    for (int o = 16; o; o >>= 1) ss += __shfl_xor_sync(0xffffffffu, ss, o);
    if (lane2 == 0) red[wid] = ss;
    __syncthreads();
    float kn = 0.f;
    #pragma unroll
    for (int i = 0; i < 8; i++) kn += red[i];
    float inv_knrm = 1.f / fmaxf(sqrtf(kn), EPS_NRM);
    __syncthreads();

    float s[8];
    float mx = -1e30f;
    #pragma unroll
    for (int i = 0; i < 8; i++) {
        s[i] = g_scores[b * NN + i * 256 + t] * inv_knrm;
        mx = fmaxf(mx, s[i]);
    }
    #pragma unroll
    for (int o = 16; o; o >>= 1) mx = fmaxf(mx, __shfl_xor_sync(0xffffffffu, mx, o));
    if (lane2 == 0) red[wid] = mx;
    __syncthreads();
    float bm = red[0];
    #pragma unroll
    for (int i = 1; i < 8; i++) bm = fmaxf(bm, red[i]);
    __syncthreads();

    float e[8], sum = 0.f;
    #pragma unroll
    for (int i = 0; i < 8; i++) { e[i] = __expf(s[i] - bm); sum += e[i]; }
    #pragma unroll
    for (int o = 16; o; o >>= 1) sum += __shfl_xor_sync(0xffffffffu, sum, o);
    if (lane2 == 0) red[wid] = sum;
    __syncthreads();
    float tot = 0.f;
    #pragma unroll
    for (int i = 0; i < 8; i++) tot += red[i];
    __syncthreads();

    float inv = 1.f / tot;
    float gb  = g[b];
    float c   = 0.f;
    #pragma unroll
    for (int i = 0; i < 8; i++) {
        int n = i * 256 + t;
        float wr  = e[i] * inv;
        float lu  = (float)w_lu_prev[b * NN + n];
        float wrp = w_prev[b * 2 * NN + NN + n];     // w_prev[b,1,n]
        float ww  = gb * wrp + (1.f - gb) * lu;
        g_a[b * NN + n] = wr * (1.f - lu);
        c += wr * ww;
    }
    #pragma unroll
    for (int o = 16; o; o >>= 1) c += __shfl_xor_sync(0xffffffffu, c, o);
    if (lane2 == 0) red[wid] = c;
    __syncthreads();
    if (t == 0) {
        float ctot = 0.f;
        #pragma unroll
        for (int i = 0; i < 8; i++) ctot += red[i];
        g_c[b] = ctot;
        g_cnt_a[b] = 0u;   // reset for next graph replay (after all reads above)
    }
}

// ===================================================================
// Kernel B: read reduction (streaming pass 2) + fused final sum.
// grid = (BB, NSPLIT), block = 256 = 4 n-slices x 64 float4-columns.
// Last block of each b sums the 16 partials + c*k and writes out.
// ===================================================================
__global__ void __launch_bounds__(256)
read_kernel(const float4* __restrict__ mem4,
            const float*  __restrict__ k,
            float* __restrict__ out) {
    int b     = blockIdx.x;
    int split = blockIdx.y;
    int t     = threadIdx.x;
    int c4    = t & 63;       // float4 column in [0,64)
    int slice = t >> 6;       // n-slice in [0,4)

    __shared__ float a[CHUNK];
    __shared__ float4 red[256];
    __shared__ unsigned int s_old;

    int n0 = split * CHUNK;
    if (t < CHUNK) a[t] = g_a[b * NN + n0 + t];
    __syncthreads();

    const float4* p = mem4 + ((size_t)(b * NN + n0)) * 64 + c4;
    float4 acc = make_float4(0.f, 0.f, 0.f, 0.f);
    #pragma unroll 4
    for (int i = slice; i < CHUNK; i += 4) {
        float4 v = p[(size_t)i * 64];
        float  w = a[i];
        acc.x = fmaf(w, v.x, acc.x);
        acc.y = fmaf(w, v.y, acc.y);
        acc.z = fmaf(w, v.z, acc.z);
        acc.w = fmaf(w, v.w, acc.w);
    }
    red[t] = acc;
    __syncthreads();

    if (slice == 0) {
        float4 r0 = red[c4], r1 = red[c4 + 64], r2 = red[c4 + 128], r3 = red[c4 + 192];
        float4 s;
        s.x = (r0.x + r1.x) + (r2.x + r3.x);
        s.y = (r0.y + r1.y) + (r2.y + r3.y);
        s.z = (r0.z + r1.z) + (r2.z + r3.z);
        s.w = (r0.w + r1.w) + (r2.w + r3.w);
        ((float4*)g_part)[(b * NSPLIT + split) * 64 + c4] = s;
    }

    // ---- handoff: last block of this b does the final reduce ----
    __syncthreads();
    __threadfence();                       // release: partials visible
    if (t == 0) s_old = atomicAdd(&g_cnt_b[b], 1u);
    __syncthreads();
    if (s_old != NSPLIT - 1) return;
    __threadfence();                       // acquire: see all partials

    // final reduce as float4: 64 lanes cover the 64 float4-columns;
    // threads 64..255 idle here (tail is tiny).
    if (t < 64) {
        const float4* pp = (const float4*)g_part + b * NSPLIT * 64 + t;
        float4 s = make_float4(0.f, 0.f, 0.f, 0.f);
        #pragma unroll
        for (int sp = 0; sp < NSPLIT; sp++) {
            float4 v = pp[sp * 64];
            s.x += v.x; s.y += v.y; s.z += v.z; s.w += v.w;
        }
        float c = g_c[b];
        const float4* k4 = (const float4*)k + b * 64 + t;
        float4 kv = *k4;
        float4 o;
        o.x = fmaf(c, kv.x, s.x);
        o.y = fmaf(c, kv.y, s.y);
        o.z = fmaf(c, kv.z, s.z);
        o.w = fmaf(c, kv.w, s.w);
        ((float4*)out)[b * 64 + t] = o;
    }

    if (t == 0) g_cnt_b[b] = 0u;   // reset for next graph replay
}

// -------------------------------------------------------------------
extern "C" void kernel_launch(void* const* d_in, const int* in_sizes, int n_in,
                              void* d_out, int out_size) {
    const float* memory    = (const float*)d_in[0];   // (B,N,M)
    const float* k         = (const float*)d_in[1];   // (B,M)
    const float* g         = (const float*)d_in[2];   // (B,1)
    // d_in[3] = gamma  -> dead code w.r.t. output
    const float* w_prev    = (const float*)d_in[4];   // (B,2,N)
    const int*   w_lu_prev = (const int*)  d_in[5];   // (B,N)
    // d_in[6] = n      -> dead code w.r.t. output
    float* out = (float*)d_out;                        // (B,M)

    score_softmax_kernel<<<dim3(BB, NSPLIT), 256>>>(
        (const float4*)memory, k, g, w_prev, w_lu_prev);
    read_kernel<<<dim3(BB, NSPLIT), 256>>>(
        (const float4*)memory, k, out);
}

// round 13
// speedup vs baseline: 1.1694x; 1.1694x over previous
#include <cuda_runtime.h>
#include <math.h>

// Fixed problem shape (B, N, M) = (64, 2048, 256)
#define BB 64
#define NN 2048
#define MM 256
#define EPS_COS 1e-16f
#define EPS_NRM 1e-8f
#define NSPLIT 16            // blocks per b in pass 2
#define CHUNK (NN / NSPLIT)  // 128 rows per block

// Static scratch (allocation-free rule). Zero-initialized at module load.
__device__ float g_scores[BB * NN];          // dot/mem_nrm (k_nrm applied in softmax)
__device__ float g_a[BB * NN];               // w_r * (1 - w_lu_prev)
__device__ float g_c[BB];                    // sum(w_r * w_w)
__device__ float g_part[BB * NSPLIT * MM];
__device__ unsigned int g_cnt_b[BB];         // pass-2 handoff counters

// ===================================================================
// Kernel 1: score pass (R3-measured version). One warp per (b,n) row,
// one-shot blocks (grid 16384) for maximal block-level MLP.
// Reads memory in ASCENDING address order.
// ===================================================================
__global__ void __launch_bounds__(256)
score_kernel(const float4* __restrict__ mem4,
             const float* __restrict__ k) {
    int warp = threadIdx.x >> 5;
    int lane = threadIdx.x & 31;
    int row  = blockIdx.x * 8 + warp;          // row in [0, B*N)
    int b    = row >> 11;                      // N = 2048; 8 rows never straddle b

    __shared__ float ke[MM];
    ke[threadIdx.x] = k[b * MM + threadIdx.x] + EPS_COS;
    __syncthreads();

    const float4* p = mem4 + (size_t)row * (MM / 4) + lane * 2;
    float4 v0 = p[0];
    float4 v1 = p[1];
    int m0 = lane * 8;

    float dot = 0.f, ss = 0.f, me;
    me = v0.x + EPS_COS; dot = fmaf(me, ke[m0 + 0], dot); ss = fmaf(me, me, ss);
    me = v0.y + EPS_COS; dot = fmaf(me, ke[m0 + 1], dot); ss = fmaf(me, me, ss);
    me = v0.z + EPS_COS; dot = fmaf(me, ke[m0 + 2], dot); ss = fmaf(me, me, ss);
    me = v0.w + EPS_COS; dot = fmaf(me, ke[m0 + 3], dot); ss = fmaf(me, me, ss);
    me = v1.x + EPS_COS; dot = fmaf(me, ke[m0 + 4], dot); ss = fmaf(me, me, ss);
    me = v1.y + EPS_COS; dot = fmaf(me, ke[m0 + 5], dot); ss = fmaf(me, me, ss);
    me = v1.z + EPS_COS; dot = fmaf(me, ke[m0 + 6], dot); ss = fmaf(me, me, ss);
    me = v1.w + EPS_COS; dot = fmaf(me, ke[m0 + 7], dot); ss = fmaf(me, me, ss);

    #pragma unroll
    for (int o = 16; o; o >>= 1) {
        dot += __shfl_xor_sync(0xffffffffu, dot, o);
        ss  += __shfl_xor_sync(0xffffffffu, ss,  o);
    }
    if (lane == 0) {
        float nrm = fmaxf(sqrtf(ss), EPS_NRM);
        g_scores[row] = dot / nrm;
    }
}

// ===================================================================
// Kernel 2: per-b softmax over N=2048 scores; writes g_a and g_c.
// grid = B, block = 256 (8 scores per thread).
// ===================================================================
__global__ void __launch_bounds__(256)
softmax_kernel(const float* __restrict__ k,
               const float* __restrict__ g,
               const float* __restrict__ w_prev,
               const int*   __restrict__ w_lu_prev) {
    int b = blockIdx.x;
    int t = threadIdx.x;
    int lane = t & 31, wid = t >> 5;
    __shared__ float red[8];

    // ---- k_nrm for this b ----
    float kv = k[b * MM + t] + EPS_COS;
    float ss = kv * kv;
    #pragma unroll
    for (int o = 16; o; o >>= 1) ss += __shfl_xor_sync(0xffffffffu, ss, o);
    if (lane == 0) red[wid] = ss;
    __syncthreads();
    float kn = 0.f;
    #pragma unroll
    for (int i = 0; i < 8; i++) kn += red[i];
    float inv_knrm = 1.f / fmaxf(sqrtf(kn), EPS_NRM);
    __syncthreads();

    // ---- softmax over scaled logits ----
    float s[8];
    float mx = -1e30f;
    #pragma unroll
    for (int i = 0; i < 8; i++) {
        s[i] = g_scores[b * NN + i * 256 + t] * inv_knrm;
        mx = fmaxf(mx, s[i]);
    }
    #pragma unroll
    for (int o = 16; o; o >>= 1) mx = fmaxf(mx, __shfl_xor_sync(0xffffffffu, mx, o));
    if (lane == 0) red[wid] = mx;
    __syncthreads();
    float bm = red[0];
    #pragma unroll
    for (int i = 1; i < 8; i++) bm = fmaxf(bm, red[i]);
    __syncthreads();

    float e[8], sum = 0.f;
    #pragma unroll
    for (int i = 0; i < 8; i++) { e[i] = __expf(s[i] - bm); sum += e[i]; }
    #pragma unroll
    for (int o = 16; o; o >>= 1) sum += __shfl_xor_sync(0xffffffffu, sum, o);
    if (lane == 0) red[wid] = sum;
    __syncthreads();
    float tot = 0.f;
    #pragma unroll
    for (int i = 0; i < 8; i++) tot += red[i];
    __syncthreads();

    // ---- a[b,n] and scalar c ----
    float inv = 1.f / tot;
    float gb  = g[b];
    float c   = 0.f;
    #pragma unroll
    for (int i = 0; i < 8; i++) {
        int n = i * 256 + t;
        float wr  = e[i] * inv;
        float lu  = (float)w_lu_prev[b * NN + n];
        float wrp = w_prev[b * 2 * NN + NN + n];      // w_prev[b,1,n]
        float ww  = gb * wrp + (1.f - gb) * lu;
        g_a[b * NN + n] = wr * (1.f - lu);
        c += wr * ww;
    }
    #pragma unroll
    for (int o = 16; o; o >>= 1) c += __shfl_xor_sync(0xffffffffu, c, o);
    if (lane == 0) red[wid] = c;
    __syncthreads();
    if (t == 0) {
        float ctot = 0.f;
        #pragma unroll
        for (int i = 0; i < 8; i++) ctot += red[i];
        g_c[b] = ctot;
    }
}

// ===================================================================
// Kernel 3: read reduction (pass 2) + fused final sum.
// grid = (BB, NSPLIT), block = 256 = 4 n-slices x 64 float4-columns.
// REVERSED traversal: block bid 0 handles the HIGHEST addresses (the
// freshest lines in L2 from pass 1) and rows iterate descending, so the
// re-read runs anti-LRU and hits L2 instead of chasing evictions.
// Last block of each b sums the 16 partials + c*k and writes out.
// ===================================================================
__global__ void __launch_bounds__(256)
read_kernel(const float4* __restrict__ mem4,
            const float*  __restrict__ k,
            float* __restrict__ out) {
    int b     = BB - 1 - (int)blockIdx.x;        // reversed mapping
    int split = NSPLIT - 1 - (int)blockIdx.y;    // reversed mapping
    int t     = threadIdx.x;
    int c4    = t & 63;       // float4 column in [0,64)
    int slice = t >> 6;       // n-slice in [0,4)

    __shared__ float a[CHUNK];
    __shared__ float4 red[256];
    __shared__ unsigned int s_old;

    int n0 = split * CHUNK;
    if (t < CHUNK) a[t] = g_a[b * NN + n0 + t];
    __syncthreads();

    const float4* p = mem4 + ((size_t)(b * NN + n0)) * 64 + c4;
    float4 acc = make_float4(0.f, 0.f, 0.f, 0.f);
    // descending row groups: i = 124+slice, 120+slice, ..., 0+slice
    #pragma unroll 4
    for (int j = 0; j < CHUNK / 4; j++) {
        int i = (CHUNK - 4 - j * 4) + slice;
        float4 v = p[(size_t)i * 64];
        float  w = a[i];
        acc.x = fmaf(w, v.x, acc.x);
        acc.y = fmaf(w, v.y, acc.y);
        acc.z = fmaf(w, v.z, acc.z);
        acc.w = fmaf(w, v.w, acc.w);
    }
    red[t] = acc;
    __syncthreads();

    if (slice == 0) {
        float4 r0 = red[c4], r1 = red[c4 + 64], r2 = red[c4 + 128], r3 = red[c4 + 192];
        float4 s;
        s.x = (r0.x + r1.x) + (r2.x + r3.x);
        s.y = (r0.y + r1.y) + (r2.y + r3.y);
        s.z = (r0.z + r1.z) + (r2.z + r3.z);
        s.w = (r0.w + r1.w) + (r2.w + r3.w);
        ((float4*)g_part)[(b * NSPLIT + split) * 64 + c4] = s;
    }

    // ---- handoff: last block of this b does the final reduce ----
    __syncthreads();
    __threadfence();                       // release: partials visible
    if (t == 0) s_old = atomicAdd(&g_cnt_b[b], 1u);
    __syncthreads();
    if (s_old != NSPLIT - 1) return;
    __threadfence();                       // acquire: see all partials

    if (t < 64) {
        const float4* pp = (const float4*)g_part + b * NSPLIT * 64 + t;
        float4 s = make_float4(0.f, 0.f, 0.f, 0.f);
        #pragma unroll
        for (int sp = 0; sp < NSPLIT; sp++) {
            float4 v = pp[sp * 64];
            s.x += v.x; s.y += v.y; s.z += v.z; s.w += v.w;
        }
        float c = g_c[b];
        float4 kv = ((const float4*)k)[b * 64 + t];
        float4 o;
        o.x = fmaf(c, kv.x, s.x);
        o.y = fmaf(c, kv.y, s.y);
        o.z = fmaf(c, kv.z, s.z);
        o.w = fmaf(c, kv.w, s.w);
        ((float4*)out)[b * 64 + t] = o;
    }

    if (t == 0) g_cnt_b[b] = 0u;   // reset for next graph replay
}

// -------------------------------------------------------------------
extern "C" void kernel_launch(void* const* d_in, const int* in_sizes, int n_in,
                              void* d_out, int out_size) {
    const float* memory    = (const float*)d_in[0];   // (B,N,M)
    const float* k         = (const float*)d_in[1];   // (B,M)
    const float* g         = (const float*)d_in[2];   // (B,1)
    // d_in[3] = gamma  -> dead code w.r.t. output
    const float* w_prev    = (const float*)d_in[4];   // (B,2,N)
    const int*   w_lu_prev = (const int*)  d_in[5];   // (B,N)
    // d_in[6] = n      -> dead code w.r.t. output
    float* out = (float*)d_out;                        // (B,M)

    score_kernel<<<BB * NN / 8, 256>>>((const float4*)memory, k);
    softmax_kernel<<<BB, 256>>>(k, g, w_prev, w_lu_prev);
    read_kernel<<<dim3(BB, NSPLIT), 256>>>((const float4*)memory, k, out);
}

// round 14
// speedup vs baseline: 1.2268x; 1.0491x over previous
#include <cuda_runtime.h>
#include <math.h>

// Fixed problem shape (B, N, M) = (64, 2048, 256)
#define BB 64
#define NN 2048
#define MM 256
#define EPS_COS 1e-16f
#define EPS_NRM 1e-8f
#define NSPLIT 16            // blocks per b in pass 2
#define CHUNK (NN / NSPLIT)  // 128 rows per block

// Static scratch (allocation-free rule). Zero-initialized at module load.
__device__ float g_scores[BB * NN];          // dot/mem_nrm (k_nrm applied in softmax)
__device__ float g_a[BB * NN];               // w_r * (1 - w_lu_prev)
__device__ float g_c[BB];                    // sum(w_r * w_w)
__device__ float g_part[BB * NSPLIT * MM];
__device__ unsigned int g_cnt_b[BB];         // pass-2 handoff counters

// ===================================================================
// Kernel 1: score pass. One warp per (b,n) row, one-shot blocks.
// k values held in REGISTERS (2x float4 per lane, L1/L2-resident) —
// no shared memory, no bank conflicts, no __syncthreads.
// ===================================================================
__global__ void __launch_bounds__(256)
score_kernel(const float4* __restrict__ mem4,
             const float4* __restrict__ k4) {
    int warp = threadIdx.x >> 5;
    int lane = threadIdx.x & 31;
    int row  = blockIdx.x * 8 + warp;          // row in [0, B*N)
    int b    = row >> 11;                      // N = 2048; 8 rows never straddle b

    // per-lane k slice in registers: k[b, lane*8 .. lane*8+7]
    float4 ka = k4[b * 64 + lane * 2];
    float4 kb = k4[b * 64 + lane * 2 + 1];
    ka.x += EPS_COS; ka.y += EPS_COS; ka.z += EPS_COS; ka.w += EPS_COS;
    kb.x += EPS_COS; kb.y += EPS_COS; kb.z += EPS_COS; kb.w += EPS_COS;

    const float4* p = mem4 + (size_t)row * (MM / 4) + lane * 2;
    float4 v0 = p[0];
    float4 v1 = p[1];

    float dot = 0.f, ss = 0.f, me;
    me = v0.x + EPS_COS; dot = fmaf(me, ka.x, dot); ss = fmaf(me, me, ss);
    me = v0.y + EPS_COS; dot = fmaf(me, ka.y, dot); ss = fmaf(me, me, ss);
    me = v0.z + EPS_COS; dot = fmaf(me, ka.z, dot); ss = fmaf(me, me, ss);
    me = v0.w + EPS_COS; dot = fmaf(me, ka.w, dot); ss = fmaf(me, me, ss);
    me = v1.x + EPS_COS; dot = fmaf(me, kb.x, dot); ss = fmaf(me, me, ss);
    me = v1.y + EPS_COS; dot = fmaf(me, kb.y, dot); ss = fmaf(me, me, ss);
    me = v1.z + EPS_COS; dot = fmaf(me, kb.z, dot); ss = fmaf(me, me, ss);
    me = v1.w + EPS_COS; dot = fmaf(me, kb.w, dot); ss = fmaf(me, me, ss);

    #pragma unroll
    for (int o = 16; o; o >>= 1) {
        dot += __shfl_xor_sync(0xffffffffu, dot, o);
        ss  += __shfl_xor_sync(0xffffffffu, ss,  o);
    }
    if (lane == 0) {
        float nrm = fmaxf(sqrtf(ss), EPS_NRM);
        g_scores[row] = dot / nrm;
    }
}

// ===================================================================
// Kernel 2: per-b softmax over N=2048 scores; writes g_a and g_c.
// grid = B, block = 256 (8 scores per thread).
// ===================================================================
__global__ void __launch_bounds__(256)
softmax_kernel(const float* __restrict__ k,
               const float* __restrict__ g,
               const float* __restrict__ w_prev,
               const int*   __restrict__ w_lu_prev) {
    int b = blockIdx.x;
    int t = threadIdx.x;
    int lane = t & 31, wid = t >> 5;
    __shared__ float red[8];

    // ---- k_nrm for this b ----
    float kv = k[b * MM + t] + EPS_COS;
    float ss = kv * kv;
    #pragma unroll
    for (int o = 16; o; o >>= 1) ss += __shfl_xor_sync(0xffffffffu, ss, o);
    if (lane == 0) red[wid] = ss;
    __syncthreads();
    float kn = 0.f;
    #pragma unroll
    for (int i = 0; i < 8; i++) kn += red[i];
    float inv_knrm = 1.f / fmaxf(sqrtf(kn), EPS_NRM);
    __syncthreads();

    // ---- softmax over scaled logits ----
    float s[8];
    float mx = -1e30f;
    #pragma unroll
    for (int i = 0; i < 8; i++) {
        s[i] = g_scores[b * NN + i * 256 + t] * inv_knrm;
        mx = fmaxf(mx, s[i]);
    }
    #pragma unroll
    for (int o = 16; o; o >>= 1) mx = fmaxf(mx, __shfl_xor_sync(0xffffffffu, mx, o));
    if (lane == 0) red[wid] = mx;
    __syncthreads();
    float bm = red[0];
    #pragma unroll
    for (int i = 1; i < 8; i++) bm = fmaxf(bm, red[i]);
    __syncthreads();

    float e[8], sum = 0.f;
    #pragma unroll
    for (int i = 0; i < 8; i++) { e[i] = __expf(s[i] - bm); sum += e[i]; }
    #pragma unroll
    for (int o = 16; o; o >>= 1) sum += __shfl_xor_sync(0xffffffffu, sum, o);
    if (lane == 0) red[wid] = sum;
    __syncthreads();
    float tot = 0.f;
    #pragma unroll
    for (int i = 0; i < 8; i++) tot += red[i];
    __syncthreads();

    // ---- a[b,n] and scalar c ----
    float inv = 1.f / tot;
    float gb  = g[b];
    float c   = 0.f;
    #pragma unroll
    for (int i = 0; i < 8; i++) {
        int n = i * 256 + t;
        float wr  = e[i] * inv;
        float lu  = (float)w_lu_prev[b * NN + n];
        float wrp = w_prev[b * 2 * NN + NN + n];      // w_prev[b,1,n]
        float ww  = gb * wrp + (1.f - gb) * lu;
        g_a[b * NN + n] = wr * (1.f - lu);
        c += wr * ww;
    }
    #pragma unroll
    for (int o = 16; o; o >>= 1) c += __shfl_xor_sync(0xffffffffu, c, o);
    if (lane == 0) red[wid] = c;
    __syncthreads();
    if (t == 0) {
        float ctot = 0.f;
        #pragma unroll
        for (int i = 0; i < 8; i++) ctot += red[i];
        g_c[b] = ctot;
    }
}

// ===================================================================
// Kernel 3: read reduction (pass 2) + fused final sum.
// grid = (BB, NSPLIT), block = 256 = 4 n-slices x 64 float4-columns.
// REVERSED traversal (measured win): highest addresses first, rows
// descending, so the re-read runs anti-LRU against pass 1's L2 state.
// Last block of each b sums the 16 partials + c*k and writes out.
// ===================================================================
__global__ void __launch_bounds__(256)
read_kernel(const float4* __restrict__ mem4,
            const float*  __restrict__ k,
            float* __restrict__ out) {
    int b     = BB - 1 - (int)blockIdx.x;        // reversed mapping
    int split = NSPLIT - 1 - (int)blockIdx.y;    // reversed mapping
    int t     = threadIdx.x;
    int c4    = t & 63;       // float4 column in [0,64)
    int slice = t >> 6;       // n-slice in [0,4)

    __shared__ float a[CHUNK];
    __shared__ float4 red[256];
    __shared__ unsigned int s_old;

    int n0 = split * CHUNK;
    if (t < CHUNK) a[t] = g_a[b * NN + n0 + t];
    __syncthreads();

    const float4* p = mem4 + ((size_t)(b * NN + n0)) * 64 + c4;
    float4 acc = make_float4(0.f, 0.f, 0.f, 0.f);
    // descending row groups: i = 124+slice, 120+slice, ..., 0+slice
    #pragma unroll 4
    for (int j = 0; j < CHUNK / 4; j++) {
        int i = (CHUNK - 4 - j * 4) + slice;
        float4 v = p[(size_t)i * 64];
        float  w = a[i];
        acc.x = fmaf(w, v.x, acc.x);
        acc.y = fmaf(w, v.y, acc.y);
        acc.z = fmaf(w, v.z, acc.z);
        acc.w = fmaf(w, v.w, acc.w);
    }
    red[t] = acc;
    __syncthreads();

    if (slice == 0) {
        float4 r0 = red[c4], r1 = red[c4 + 64], r2 = red[c4 + 128], r3 = red[c4 + 192];
        float4 s;
        s.x = (r0.x + r1.x) + (r2.x + r3.x);
        s.y = (r0.y + r1.y) + (r2.y + r3.y);
        s.z = (r0.z + r1.z) + (r2.z + r3.z);
        s.w = (r0.w + r1.w) + (r2.w + r3.w);
        ((float4*)g_part)[(b * NSPLIT + split) * 64 + c4] = s;
    }

    // ---- handoff: last block of this b does the final reduce ----
    __syncthreads();
    __threadfence();                       // release: partials visible
    if (t == 0) s_old = atomicAdd(&g_cnt_b[b], 1u);
    __syncthreads();
    if (s_old != NSPLIT - 1) return;
    __threadfence();                       // acquire: see all partials

    if (t < 64) {
        const float4* pp = (const float4*)g_part + b * NSPLIT * 64 + t;
        float4 s = make_float4(0.f, 0.f, 0.f, 0.f);
        #pragma unroll
        for (int sp = 0; sp < NSPLIT; sp++) {
            float4 v = pp[sp * 64];
            s.x += v.x; s.y += v.y; s.z += v.z; s.w += v.w;
        }
        float c = g_c[b];
        float4 kv = ((const float4*)k)[b * 64 + t];
        float4 o;
        o.x = fmaf(c, kv.x, s.x);
        o.y = fmaf(c, kv.y, s.y);
        o.z = fmaf(c, kv.z, s.z);
        o.w = fmaf(c, kv.w, s.w);
        ((float4*)out)[b * 64 + t] = o;
    }

    if (t == 0) g_cnt_b[b] = 0u;   // reset for next graph replay
}

// -------------------------------------------------------------------
extern "C" void kernel_launch(void* const* d_in, const int* in_sizes, int n_in,
                              void* d_out, int out_size) {
    const float* memory    = (const float*)d_in[0];   // (B,N,M)
    const float* k         = (const float*)d_in[1];   // (B,M)
    const float* g         = (const float*)d_in[2];   // (B,1)
    // d_in[3] = gamma  -> dead code w.r.t. output
    const float* w_prev    = (const float*)d_in[4];   // (B,2,N)
    const int*   w_lu_prev = (const int*)  d_in[5];   // (B,N)
    // d_in[6] = n      -> dead code w.r.t. output
    float* out = (float*)d_out;                        // (B,M)

    score_kernel<<<BB * NN / 8, 256>>>((const float4*)memory, (const float4*)k);
    softmax_kernel<<<BB, 256>>>(k, g, w_prev, w_lu_prev);
    read_kernel<<<dim3(BB, NSPLIT), 256>>>((const float4*)memory, k, out);
}

// round 15
// speedup vs baseline: 1.5034x; 1.2254x over previous
#include <cuda_runtime.h>
#include <math.h>

// Fixed problem shape (B, N, M) = (64, 2048, 256)
#define BB 64
#define NN 2048
#define MM 256
#define EPS_COS 1e-16f
#define EPS_NRM 1e-8f
#define NSPLIT 16            // blocks per b
#define CHUNK (NN / NSPLIT)  // 128 rows per block (8 warps x 16 rows)

// Static scratch (allocation-free rule). Zero-initialized at module load.
__device__ float g_pmax[BB * NSPLIT];
__device__ float g_psum[BB * NSPLIT];
__device__ float g_pc[BB * NSPLIT];
__device__ float g_pacc[BB * NSPLIT * MM];
__device__ unsigned int g_cnt[BB];

// ===================================================================
// Single-pass fused kernel: online-softmax over cosine scores with
// in-register weighted accumulation — memory[] is read from DRAM ONCE.
// grid = (BB, NSPLIT), block = 256 (8 warps; warp w handles rows
// n0 + it*8 + w, it = 0..15). Each lane owns m = lane*8 .. lane*8+7.
// Last block of each b merges the 16 partials and writes out.
// ===================================================================
__global__ void __launch_bounds__(256)
fused_kernel(const float4* __restrict__ mem4,
             const float4* __restrict__ k4,
             const float*  __restrict__ kf,
             const float*  __restrict__ g,
             const float*  __restrict__ w_prev,
             const int*    __restrict__ w_lu_prev,
             float* __restrict__ out) {
    int b     = blockIdx.x;
    int split = blockIdx.y;
    int t     = threadIdx.x;
    int warp  = t >> 5;
    int lane  = t & 31;

    __shared__ float4 sacc4[8][64];     // 8 KB: per-warp scaled accumulators
    __shared__ float  smax[8], ssum[8], scp[8];
    __shared__ float  pm[NSPLIT], pw[NSPLIT], red2[2];
    __shared__ unsigned int s_old;

    // per-lane k slice (with eps) in registers: k[b, lane*8 .. lane*8+7]
    float4 ka = k4[b * 64 + lane * 2];
    float4 kb = k4[b * 64 + lane * 2 + 1];
    ka.x += EPS_COS; ka.y += EPS_COS; ka.z += EPS_COS; ka.w += EPS_COS;
    kb.x += EPS_COS; kb.y += EPS_COS; kb.z += EPS_COS; kb.w += EPS_COS;

    // inv_knrm (computed per warp from registers; uniform across warps)
    float ssk = 0.f;
    ssk = fmaf(ka.x, ka.x, ssk); ssk = fmaf(ka.y, ka.y, ssk);
    ssk = fmaf(ka.z, ka.z, ssk); ssk = fmaf(ka.w, ka.w, ssk);
    ssk = fmaf(kb.x, kb.x, ssk); ssk = fmaf(kb.y, kb.y, ssk);
    ssk = fmaf(kb.z, kb.z, ssk); ssk = fmaf(kb.w, kb.w, ssk);
    #pragma unroll
    for (int o = 16; o; o >>= 1) ssk += __shfl_xor_sync(0xffffffffu, ssk, o);
    float inv_knrm = 1.f / fmaxf(sqrtf(ssk), EPS_NRM);

    float gb = g[b];
    int   n0 = split * CHUNK;

    // online-softmax state (per warp; s values are warp-uniform)
    float wmax = -1e30f, wsum = 0.f, cpart = 0.f;
    float4 a0 = make_float4(0.f, 0.f, 0.f, 0.f);
    float4 a1 = make_float4(0.f, 0.f, 0.f, 0.f);

    for (int it = 0; it < CHUNK / 8; it++) {
        int n = n0 + it * 8 + warp;
        const float4* p = mem4 + ((size_t)(b * NN + n)) * 64 + lane * 2;
        float4 v0 = p[0];
        float4 v1 = p[1];

        float dot = 0.f, ss = 0.f, me;
        me = v0.x + EPS_COS; dot = fmaf(me, ka.x, dot); ss = fmaf(me, me, ss);
        me = v0.y + EPS_COS; dot = fmaf(me, ka.y, dot); ss = fmaf(me, me, ss);
        me = v0.z + EPS_COS; dot = fmaf(me, ka.z, dot); ss = fmaf(me, me, ss);
        me = v0.w + EPS_COS; dot = fmaf(me, ka.w, dot); ss = fmaf(me, me, ss);
        me = v1.x + EPS_COS; dot = fmaf(me, kb.x, dot); ss = fmaf(me, me, ss);
        me = v1.y + EPS_COS; dot = fmaf(me, kb.y, dot); ss = fmaf(me, me, ss);
        me = v1.z + EPS_COS; dot = fmaf(me, kb.z, dot); ss = fmaf(me, me, ss);
        me = v1.w + EPS_COS; dot = fmaf(me, kb.w, dot); ss = fmaf(me, me, ss);
        #pragma unroll
        for (int o = 16; o; o >>= 1) {
            dot += __shfl_xor_sync(0xffffffffu, dot, o);
            ss  += __shfl_xor_sync(0xffffffffu, ss,  o);
        }
        float s = dot / fmaxf(sqrtf(ss), EPS_NRM) * inv_knrm;

        float lu  = (float)w_lu_prev[b * NN + n];     // warp-uniform LDG
        float wrp = w_prev[b * 2 * NN + NN + n];      // w_prev[b,1,n]
        float ww  = gb * wrp + (1.f - gb) * lu;

        float mnew = fmaxf(wmax, s);
        float sc   = __expf(wmax - mnew);
        float ex   = __expf(s - mnew);
        wsum  = wsum  * sc + ex;
        cpart = cpart * sc + ex * ww;
        float f = ex * (1.f - lu);
        a0.x = fmaf(a0.x, sc, f * v0.x);
        a0.y = fmaf(a0.y, sc, f * v0.y);
        a0.z = fmaf(a0.z, sc, f * v0.z);
        a0.w = fmaf(a0.w, sc, f * v0.w);
        a1.x = fmaf(a1.x, sc, f * v1.x);
        a1.y = fmaf(a1.y, sc, f * v1.y);
        a1.z = fmaf(a1.z, sc, f * v1.z);
        a1.w = fmaf(a1.w, sc, f * v1.w);
        wmax = mnew;
    }

    // ---- block merge across 8 warps ----
    if (lane == 0) smax[warp] = wmax;
    __syncthreads();
    float bmax = smax[0];
    #pragma unroll
    for (int i = 1; i < 8; i++) bmax = fmaxf(bmax, smax[i]);
    float wscale = __expf(wmax - bmax);
    sacc4[warp][lane * 2].x     = a0.x * wscale;
    sacc4[warp][lane * 2].y     = a0.y * wscale;
    sacc4[warp][lane * 2].z     = a0.z * wscale;
    sacc4[warp][lane * 2].w     = a0.w * wscale;
    sacc4[warp][lane * 2 + 1].x = a1.x * wscale;
    sacc4[warp][lane * 2 + 1].y = a1.y * wscale;
    sacc4[warp][lane * 2 + 1].z = a1.z * wscale;
    sacc4[warp][lane * 2 + 1].w = a1.w * wscale;
    if (lane == 0) { ssum[warp] = wsum * wscale; scp[warp] = cpart * wscale; }
    __syncthreads();

    int idx = b * NSPLIT + split;
    {
        const float* sa = (const float*)sacc4;     // [8][256]
        float v = 0.f;
        #pragma unroll
        for (int w = 0; w < 8; w++) v += sa[w * MM + t];
        g_pacc[idx * MM + t] = v;
    }
    if (t == 0) {
        float bs = 0.f, bc = 0.f;
        #pragma unroll
        for (int i = 0; i < 8; i++) { bs += ssum[i]; bc += scp[i]; }
        g_pmax[idx] = bmax;
        g_psum[idx] = bs;
        g_pc[idx]   = bc;
    }

    // ---- handoff: last block of this b merges the 16 partials ----
    __syncthreads();
    __threadfence();                      // release
    if (t == 0) s_old = atomicAdd(&g_cnt[b], 1u);
    __syncthreads();
    if (s_old != NSPLIT - 1) return;
    __threadfence();                      // acquire

    if (t < NSPLIT) pm[t] = g_pmax[b * NSPLIT + t];
    __syncthreads();
    float gmax = pm[0];
    #pragma unroll
    for (int i = 1; i < NSPLIT; i++) gmax = fmaxf(gmax, pm[i]);
    if (t < NSPLIT) pw[t] = __expf(pm[t] - gmax);
    __syncthreads();
    if (t == 0) {
        float Z = 0.f, C = 0.f;
        #pragma unroll
        for (int s = 0; s < NSPLIT; s++) {
            Z += pw[s] * g_psum[b * NSPLIT + s];
            C += pw[s] * g_pc[b * NSPLIT + s];
        }
        red2[0] = 1.f / Z;
        red2[1] = C;
    }
    __syncthreads();
    float invZ = red2[0], C = red2[1];

    float r = 0.f;
    #pragma unroll
    for (int s = 0; s < NSPLIT; s++)
        r += pw[s] * g_pacc[(b * NSPLIT + s) * MM + t];
    out[b * MM + t] = (r + C * kf[b * MM + t]) * invZ;

    if (t == 0) g_cnt[b] = 0u;           // reset for next graph replay
}

// -------------------------------------------------------------------
extern "C" void kernel_launch(void* const* d_in, const int* in_sizes, int n_in,
                              void* d_out, int out_size) {
    const float* memory    = (const float*)d_in[0];   // (B,N,M)
    const float* k         = (const float*)d_in[1];   // (B,M)
    const float* g         = (const float*)d_in[2];   // (B,1)
    // d_in[3] = gamma  -> dead code w.r.t. output
    const float* w_prev    = (const float*)d_in[4];   // (B,2,N)
    const int*   w_lu_prev = (const int*)  d_in[5];   // (B,N)
    // d_in[6] = n      -> dead code w.r.t. output
    float* out = (float*)d_out;                        // (B,M)

    fused_kernel<<<dim3(BB, NSPLIT), 256>>>(
        (const float4*)memory, (const float4*)k, k, g, w_prev, w_lu_prev, out);
}

// round 16
// speedup vs baseline: 1.6036x; 1.0666x over previous
#include <cuda_runtime.h>
#include <math.h>

// Fixed problem shape (B, N, M) = (64, 2048, 256)
#define BB 64
#define NN 2048
#define MM 256
#define EPS_COS 1e-16f
#define EPS_NRM 1e-8f
#define NSPLIT 16            // blocks per b
#define CHUNK (NN / NSPLIT)  // 128 rows per block (8 warps x 16 rows)

// Static scratch (allocation-free rule). Zero-initialized at module load.
__device__ float g_psum[BB * NSPLIT];
__device__ float g_pc[BB * NSPLIT];
__device__ float g_pacc[BB * NSPLIT * MM];
__device__ unsigned int g_cnt[BB];

// ===================================================================
// Single-pass fused kernel, max-free softmax: logits are cosines in
// [-1,1], so exp(s) never overflows and no running max / rescale is
// needed. memory[] read from DRAM exactly once. Partials combine by
// plain addition. grid = (BB, NSPLIT), block = 256 (8 warps).
// Last block of each b merges the 16 partials and writes out.
// ===================================================================
__global__ void __launch_bounds__(256)
fused_kernel(const float4* __restrict__ mem4,
             const float4* __restrict__ k4,
             const float*  __restrict__ kf,
             const float*  __restrict__ g,
             const float*  __restrict__ w_prev,
             const int*    __restrict__ w_lu_prev,
             float* __restrict__ out) {
    int b     = blockIdx.x;
    int split = blockIdx.y;
    int t     = threadIdx.x;
    int warp  = t >> 5;
    int lane  = t & 31;

    __shared__ float4 sacc4[8][64];     // 8 KB: per-warp accumulators
    __shared__ float  ssum[8], scp[8], red2[2];
    __shared__ unsigned int s_old;

    // per-lane k slice (with eps) in registers: k[b, lane*8 .. lane*8+7]
    float4 ka = k4[b * 64 + lane * 2];
    float4 kb = k4[b * 64 + lane * 2 + 1];
    ka.x += EPS_COS; ka.y += EPS_COS; ka.z += EPS_COS; ka.w += EPS_COS;
    kb.x += EPS_COS; kb.y += EPS_COS; kb.z += EPS_COS; kb.w += EPS_COS;

    // inv_knrm (from registers; uniform across warps)
    float ssk = 0.f;
    ssk = fmaf(ka.x, ka.x, ssk); ssk = fmaf(ka.y, ka.y, ssk);
    ssk = fmaf(ka.z, ka.z, ssk); ssk = fmaf(ka.w, ka.w, ssk);
    ssk = fmaf(kb.x, kb.x, ssk); ssk = fmaf(kb.y, kb.y, ssk);
    ssk = fmaf(kb.z, kb.z, ssk); ssk = fmaf(kb.w, kb.w, ssk);
    #pragma unroll
    for (int o = 16; o; o >>= 1) ssk += __shfl_xor_sync(0xffffffffu, ssk, o);
    float inv_knrm = 1.f / fmaxf(sqrtf(ssk), EPS_NRM);

    float gb = g[b];
    int   n0 = split * CHUNK;

    // accumulation state (no max tracking needed: |s| <= ~1)
    float wsum = 0.f, cpart = 0.f;
    float4 a0 = make_float4(0.f, 0.f, 0.f, 0.f);
    float4 a1 = make_float4(0.f, 0.f, 0.f, 0.f);

    #pragma unroll 2
    for (int it = 0; it < CHUNK / 8; it++) {
        int n = n0 + it * 8 + warp;
        const float4* p = mem4 + ((size_t)(b * NN + n)) * 64 + lane * 2;
        float4 v0 = p[0];
        float4 v1 = p[1];

        float dot = 0.f, ss = 0.f, me;
        me = v0.x + EPS_COS; dot = fmaf(me, ka.x, dot); ss = fmaf(me, me, ss);
        me = v0.y + EPS_COS; dot = fmaf(me, ka.y, dot); ss = fmaf(me, me, ss);
        me = v0.z + EPS_COS; dot = fmaf(me, ka.z, dot); ss = fmaf(me, me, ss);
        me = v0.w + EPS_COS; dot = fmaf(me, ka.w, dot); ss = fmaf(me, me, ss);
        me = v1.x + EPS_COS; dot = fmaf(me, kb.x, dot); ss = fmaf(me, me, ss);
        me = v1.y + EPS_COS; dot = fmaf(me, kb.y, dot); ss = fmaf(me, me, ss);
        me = v1.z + EPS_COS; dot = fmaf(me, kb.z, dot); ss = fmaf(me, me, ss);
        me = v1.w + EPS_COS; dot = fmaf(me, kb.w, dot); ss = fmaf(me, me, ss);
        #pragma unroll
        for (int o = 16; o; o >>= 1) {
            dot += __shfl_xor_sync(0xffffffffu, dot, o);
            ss  += __shfl_xor_sync(0xffffffffu, ss,  o);
        }
        float s  = dot / fmaxf(sqrtf(ss), EPS_NRM) * inv_knrm;
        float ex = __expf(s);

        float lu  = (float)w_lu_prev[b * NN + n];     // warp-uniform LDG
        float wrp = w_prev[b * 2 * NN + NN + n];      // w_prev[b,1,n]
        float ww  = gb * wrp + (1.f - gb) * lu;

        wsum  += ex;
        cpart += ex * ww;
        float f = ex * (1.f - lu);
        a0.x = fmaf(f, v0.x, a0.x);
        a0.y = fmaf(f, v0.y, a0.y);
        a0.z = fmaf(f, v0.z, a0.z);
        a0.w = fmaf(f, v0.w, a0.w);
        a1.x = fmaf(f, v1.x, a1.x);
        a1.y = fmaf(f, v1.y, a1.y);
        a1.z = fmaf(f, v1.z, a1.z);
        a1.w = fmaf(f, v1.w, a1.w);
    }

    // ---- block merge across 8 warps (plain sums) ----
    sacc4[warp][lane * 2]     = a0;
    sacc4[warp][lane * 2 + 1] = a1;
    if (lane == 0) { ssum[warp] = wsum; scp[warp] = cpart; }
    __syncthreads();

    int idx = b * NSPLIT + split;
    {
        const float* sa = (const float*)sacc4;     // [8][256]
        float v = 0.f;
        #pragma unroll
        for (int w = 0; w < 8; w++) v += sa[w * MM + t];
        g_pacc[idx * MM + t] = v;
    }
    if (t == 0) {
        float bs = 0.f, bc = 0.f;
        #pragma unroll
        for (int i = 0; i < 8; i++) { bs += ssum[i]; bc += scp[i]; }
        g_psum[idx] = bs;
        g_pc[idx]   = bc;
    }

    // ---- handoff: last block of this b merges the 16 partials ----
    __syncthreads();
    __threadfence();                      // release
    if (t == 0) s_old = atomicAdd(&g_cnt[b], 1u);
    __syncthreads();
    if (s_old != NSPLIT - 1) return;
    __threadfence();                      // acquire

    if (t == 0) {
        float Z = 0.f, C = 0.f;
        #pragma unroll
        for (int s = 0; s < NSPLIT; s++) {
            Z += g_psum[b * NSPLIT + s];
            C += g_pc[b * NSPLIT + s];
        }
        red2[0] = 1.f / Z;
        red2[1] = C;
    }
    __syncthreads();
    float invZ = red2[0], C = red2[1];

    float r = 0.f;
    #pragma unroll
    for (int s = 0; s < NSPLIT; s++)
        r += g_pacc[(b * NSPLIT + s) * MM + t];
    out[b * MM + t] = (r + C * kf[b * MM + t]) * invZ;

    if (t == 0) g_cnt[b] = 0u;           // reset for next graph replay
}

// -------------------------------------------------------------------
extern "C" void kernel_launch(void* const* d_in, const int* in_sizes, int n_in,
                              void* d_out, int out_size) {
    const float* memory    = (const float*)d_in[0];   // (B,N,M)
    const float* k         = (const float*)d_in[1];   // (B,M)
    const float* g         = (const float*)d_in[2];   // (B,1)
    // d_in[3] = gamma  -> dead code w.r.t. output
    const float* w_prev    = (const float*)d_in[4];   // (B,2,N)
    const int*   w_lu_prev = (const int*)  d_in[5];   // (B,N)
    // d_in[6] = n      -> dead code w.r.t. output
    float* out = (float*)d_out;                        // (B,M)

    fused_kernel<<<dim3(BB, NSPLIT), 256>>>(
        (const float4*)memory, (const float4*)k, k, g, w_prev, w_lu_prev, out);
}